// round 3
// baseline (speedup 1.0000x reference)
#include <cuda_runtime.h>

#define MAXT 2048
#define TPB  128

// k1, k2, 1/s, s  per (t, subsystem)
__device__ float4 g_tab[MAXT * 3];
__device__ int    g_tconv;
__device__ double g_sumdet;
__device__ double g_part[1024];

// ---------------------------------------------------------------------------
// Setup: run the (data-independent) Riccati recursion for the 3 decoupled
// 2x2 subsystems, tabulating gains and innovation variances. Detect bitwise
// fp32 convergence to a fixed point; fill remainder of the table in parallel.
// Also accumulate sum_t det(S_t) = sum_t s0*s1*s2 (data independent).
// Full asymmetric P (p12 != p21 after rounding) is tracked to mirror the
// reference's fp32 matmul rounding as closely as possible.
// ---------------------------------------------------------------------------
__global__ void ekf_setup(const float* __restrict__ dyna,
                          const float* __restrict__ cov, int T)
{
    __shared__ int    s_conv[3];
    __shared__ double s_red[TPB];
    int tid = threadIdx.x;
    const float DTf = (float)(1.0 / 120.0);
    float a = 1.0f - dyna[1] * DTf;

    if (tid < 3) {
        int   sub = tid;
        float r   = cov[sub];
        float q1  = (sub < 2) ? cov[3] : cov[5];
        float q2  = (sub < 2) ? cov[4] : cov[6];
        float p11 = 0.01f, p12 = 0.0f, p21 = 0.0f, p22 = 0.01f;
        int   conv = T;
        for (int t = 0; t < T; ++t) {
            // Pp = (F P) F^T + Q  with F2 = [[1, DT],[0, a]]
            float fp00 = fmaf(DTf, p21, p11);
            float fp01 = fmaf(DTf, p22, p12);
            float fp10 = a * p21;
            float fp11 = a * p22;
            float p11p = fmaf(DTf, fp01, fp00) + q1;
            float p12p = a * fp01;
            float p21p = fmaf(DTf, fp11, fp10);
            float p22p = fmaf(fp11, a, q2);
            float s  = p11p + r;
            float si = 1.0f / s;
            float k1 = p11p * si;
            float k2 = p21p * si;
            float om = 1.0f - k1;
            float n11 = om * p11p;
            float n12 = om * p12p;
            float n21 = fmaf(-k2, p11p, p21p);
            float n22 = fmaf(-k2, p12p, p22p);
            g_tab[t * 3 + sub] = make_float4(k1, k2, si, s);
            if (n11 == p11 && n12 == p12 && n21 == p21 && n22 == p22) {
                conv = t + 1;   // all entries from index `conv` equal entry conv-1
                break;
            }
            p11 = n11; p12 = n12; p21 = n21; p22 = n22;
        }
        s_conv[sub] = conv;
    }
    __syncthreads();

    int tcm = max(s_conv[0], max(s_conv[1], s_conv[2]));

    // Parallel fill of converged tail per subsystem
    for (int sub = 0; sub < 3; ++sub) {
        int c = s_conv[sub];
        if (c < T) {
            float4 v = g_tab[(c - 1) * 3 + sub];
            for (int t = c + tid; t < T; t += blockDim.x)
                g_tab[t * 3 + sub] = v;
        }
    }
    __syncthreads();

    // sum_t det(S_t) (fp32 product to mirror reference, double accumulation)
    double d = 0.0;
    for (int t = tid; t < T; t += blockDim.x) {
        float s0 = g_tab[t * 3 + 0].w;
        float s1 = g_tab[t * 3 + 1].w;
        float s2 = g_tab[t * 3 + 2].w;
        d += (double)(s0 * s1 * s2);
    }
    s_red[tid] = d;
    __syncthreads();
    for (int off = TPB / 2; off > 0; off >>= 1) {
        if (tid < off) s_red[tid] += s_red[tid + off];
        __syncthreads();
    }
    if (tid == 0) { g_sumdet = s_red[0]; g_tconv = tcm; }
}

// ---------------------------------------------------------------------------
// Main scan: one thread per (trajectory, subsystem). Phase 1 uses the table
// (pre-convergence), phase 2 uses register-resident constant gains with a
// shortened dependency chain:
//   x1' = (1-k1)*xp1 + k1*z        (fma, depends on xp1)
//   x2' = -k2*xp1 + (a*x2 + k2*z)  (fma, depends on xp1)
//   xp1_next = fma(DT, x2', x1')
// quad accumulates y^2 (si constant, applied per 256-step chunk), chunks
// flushed into a double to bound fp32 accumulation error.
// ---------------------------------------------------------------------------
__global__ void __launch_bounds__(TPB)
ekf_main(const float* __restrict__ data, const float* __restrict__ init,
         const float* __restrict__ dyna, int B, int T)
{
    int g = blockIdx.x * TPB + threadIdx.x;
    double accd = 0.0;
    if (g < 3 * B) {
        int b = g / 3, sub = g - 3 * b;
        const float DTf = (float)(1.0 / 120.0);
        float a = 1.0f - dyna[1] * DTf;
        int i1 = (sub == 2) ? 4 : sub;
        int i2 = (sub == 2) ? 5 : sub + 2;
        float x1 = init[b * 6 + i1];
        float x2 = init[b * 6 + i2];

        int tconv = g_tconv;
        if (tconv > T) tconv = T;
        const float* zp = data + ((size_t)b * T) * 3 + sub;
        int t = 0;

        // ---- phase 1: time-varying gains from table ----
        {
            float facc = 0.0f;
            int   cnt  = 0;
            for (; t < tconv; ++t) {
                float4 tb = g_tab[t * 3 + sub];
                float  z  = __ldg(zp); zp += 3;
                float xp1 = fmaf(DTf, x2, x1);
                float xp2 = a * x2;
                float y   = z - xp1;
                x1 = fmaf(tb.x, y, xp1);
                x2 = fmaf(tb.y, y, xp2);
                facc = fmaf(y * tb.z, y, facc);
                if (++cnt == 256) { accd += (double)facc; facc = 0.0f; cnt = 0; }
            }
            accd += (double)facc;
        }

        // ---- phase 2: constant gains (post fixed-point) ----
        if (t < T) {
            float4 tc  = g_tab[(tconv - 1) * 3 + sub];
            float  k1  = tc.x, k2 = tc.y, si = tc.z;
            float  omk1  = 1.0f - k1;
            float  negk2 = -k2;
            while (t < T) {
                int   tend = min(t + 256, T);
                float facc = 0.0f;
                for (; t + 8 <= tend; t += 8) {
                    float zz[8];
#pragma unroll
                    for (int i = 0; i < 8; ++i) zz[i] = __ldg(zp + 3 * i);
                    zp += 24;
#pragma unroll
                    for (int i = 0; i < 8; ++i) {
                        float z   = zz[i];
                        float k1z = k1 * z;
                        float k2z = k2 * z;
                        float xp1 = fmaf(DTf, x2, x1);
                        float w   = fmaf(a, x2, k2z);
                        float y   = z - xp1;
                        x1 = fmaf(omk1, xp1, k1z);
                        x2 = fmaf(negk2, xp1, w);
                        facc = fmaf(y, y, facc);
                    }
                }
                for (; t < tend; ++t) {
                    float z   = __ldg(zp); zp += 3;
                    float xp1 = fmaf(DTf, x2, x1);
                    float y   = z - xp1;
                    float xp2 = a * x2;
                    x1 = fmaf(k1, y, xp1);
                    x2 = fmaf(k2, y, xp2);
                    facc = fmaf(y, y, facc);
                }
                accd += (double)(si * facc);
            }
        }
    }

    // deterministic block reduction
    __shared__ double sh[TPB];
    sh[threadIdx.x] = accd;
    __syncthreads();
    for (int off = TPB / 2; off > 0; off >>= 1) {
        if (threadIdx.x < off) sh[threadIdx.x] += sh[threadIdx.x + off];
        __syncthreads();
    }
    if (threadIdx.x == 0) g_part[blockIdx.x] = sh[0];
}

// ---------------------------------------------------------------------------
// Final: deterministic fixed-order reduction of block partials.
// loss = sum_quad / (B*T) + sum_det / T
// ---------------------------------------------------------------------------
__global__ void ekf_final(float* __restrict__ out, int nblocks, int B, int T)
{
    double s = 0.0;
    for (int i = 0; i < nblocks; ++i) s += g_part[i];
    double res = s / ((double)B * (double)T) + g_sumdet / (double)T;
    out[0] = (float)res;
}

extern "C" void kernel_launch(void* const* d_in, const int* in_sizes, int n_in,
                              void* d_out, int out_size)
{
    const float* data = (const float*)d_in[0];
    const float* init = (const float*)d_in[1];
    const float* dyna = (const float*)d_in[2];
    const float* cov  = (const float*)d_in[3];

    int B = in_sizes[1] / 6;
    int T = in_sizes[0] / (B * 3);
    if (T > MAXT) T = MAXT;  // table capacity guard (problem shape is T=2048)

    ekf_setup<<<1, TPB>>>(dyna, cov, T);

    int total  = 3 * B;
    int blocks = (total + TPB - 1) / TPB;
    if (blocks > 1024) blocks = 1024;  // g_part capacity (96 expected)
    ekf_main<<<blocks, TPB>>>(data, init, dyna, B, T);

    ekf_final<<<1, 1>>>((float*)d_out, blocks, B, T);
}

// round 4
// speedup vs baseline: 2.8919x; 2.8919x over previous
#include <cuda_runtime.h>

#define MAXT 2048
#define CTPB 96        // compute-kernel threads per block
#define NTRAJ 28       // trajectories per block
#define TS 64          // time-tile (steps)
#define ZSTRIDE 784    // smem bytes per trajectory per tile (768 data + 16 pad)

// Planar gain tables (16B-aligned tiles for cp.async)
__device__ __align__(256) float2 g_k12[MAXT * 3];   // (k1,k2)
__device__ __align__(256) float  g_si [MAXT * 3];   // 1/s
__device__ __align__(256) float  g_s  [MAXT * 3];   // s (for det sum)
__device__ int    g_tconv;
__device__ double g_sumdet;
__device__ double g_part[256];

// ---------------------------------------------------------------------------
// cp.async helpers
// ---------------------------------------------------------------------------
__device__ __forceinline__ void cp16(void* dst, const void* src) {
    unsigned s = (unsigned)__cvta_generic_to_shared(dst);
    unsigned long long g;
    asm volatile("cvta.to.global.u64 %0, %1;" : "=l"(g) : "l"(src));
    asm volatile("cp.async.cg.shared.global [%0], [%1], 16;" :: "r"(s), "l"(g) : "memory");
}
__device__ __forceinline__ void cp_commit() {
    asm volatile("cp.async.commit_group;" ::: "memory");
}
template<int N> __device__ __forceinline__ void cp_wait() {
    asm volatile("cp.async.wait_group %0;" :: "n"(N) : "memory");
}

// ---------------------------------------------------------------------------
// Setup: data-independent Riccati recursion for the 3 decoupled 2x2
// subsystems. Tabulates k1,k2,1/s (planar) and s. Bitwise fixed-point
// detection + parallel tail fill; det(S) sum is data-independent.
// ---------------------------------------------------------------------------
__global__ void ekf_setup(const float* __restrict__ dyna,
                          const float* __restrict__ cov, int T)
{
    __shared__ int    s_conv[3];
    __shared__ double s_red[128];
    int tid = threadIdx.x;
    const float DTf = (float)(1.0 / 120.0);
    float a = 1.0f - dyna[1] * DTf;

    if (tid < 3) {
        int   sub = tid;
        float r   = cov[sub];
        float q1  = (sub < 2) ? cov[3] : cov[5];
        float q2  = (sub < 2) ? cov[4] : cov[6];
        float p11 = 0.01f, p12 = 0.0f, p21 = 0.0f, p22 = 0.01f;
        int   conv = T;
        for (int t = 0; t < T; ++t) {
            float fp00 = fmaf(DTf, p21, p11);
            float fp01 = fmaf(DTf, p22, p12);
            float fp10 = a * p21;
            float fp11 = a * p22;
            float p11p = fmaf(DTf, fp01, fp00) + q1;
            float p12p = a * fp01;
            float p21p = fmaf(DTf, fp11, fp10);
            float p22p = fmaf(fp11, a, q2);
            float s  = p11p + r;
            float si = __fdividef(1.0f, s);
            float k1 = p11p * si;
            float k2 = p21p * si;
            float om = 1.0f - k1;
            float n11 = om * p11p;
            float n12 = om * p12p;
            float n21 = fmaf(-k2, p11p, p21p);
            float n22 = fmaf(-k2, p12p, p22p);
            g_k12[t * 3 + sub] = make_float2(k1, k2);
            g_si [t * 3 + sub] = si;
            g_s  [t * 3 + sub] = s;
            if (n11 == p11 && n12 == p12 && n21 == p21 && n22 == p22) {
                conv = t + 1;
                break;
            }
            p11 = n11; p12 = n12; p21 = n21; p22 = n22;
        }
        s_conv[sub] = conv;
    }
    __syncthreads();

    // parallel tail fill after bitwise convergence
    for (int sub = 0; sub < 3; ++sub) {
        int c = s_conv[sub];
        if (c < T) {
            float2 kv = g_k12[(c - 1) * 3 + sub];
            float  sv = g_si [(c - 1) * 3 + sub];
            float  st = g_s  [(c - 1) * 3 + sub];
            for (int t = c + tid; t < T; t += blockDim.x) {
                g_k12[t * 3 + sub] = kv;
                g_si [t * 3 + sub] = sv;
                g_s  [t * 3 + sub] = st;
            }
        }
    }
    __syncthreads();

    double d = 0.0;
    for (int t = tid; t < T; t += blockDim.x)
        d += (double)(g_s[t * 3 + 0] * g_s[t * 3 + 1] * g_s[t * 3 + 2]);
    s_red[tid] = d;
    __syncthreads();
    for (int off = 64; off > 0; off >>= 1) {
        if (tid < off) s_red[tid] += s_red[tid + off];
        __syncthreads();
    }
    if (tid == 0) g_sumdet = s_red[0];
}

// ---------------------------------------------------------------------------
// Main scan: 28 trajectories x 3 subsystems per block (84 compute threads,
// 96 threads drive copies). Double-buffered cp.async pipeline stages the
// measurement tile and the gain-table tile into smem; the per-step work is a
// short 3-fma chain fed from shared memory.
// ---------------------------------------------------------------------------
__global__ void __launch_bounds__(CTPB, 1)
ekf_main(const float* __restrict__ data, const float* __restrict__ init,
         const float* __restrict__ dyna, int B, int T)
{
    __shared__ __align__(16) unsigned char zraw[2][NTRAJ * ZSTRIDE]; // 43904 B
    __shared__ __align__(16) float2 kbuf[2][TS * 3];                 //  3072 B
    __shared__ __align__(16) float  sbuf[2][TS * 3];                 //  1536 B

    int tid    = threadIdx.x;
    int base_b = blockIdx.x * NTRAJ;
    int nt     = B - base_b; if (nt > NTRAJ) nt = NTRAJ;
    int Tt     = (T > MAXT) ? MAXT : T;   // table capacity guard
    int ntiles = Tt / TS;
    size_t trajBytes = (size_t)T * 12;
    const char* dbase = (const char*)data;

    auto issue_tile = [&](int tile) {
        int buf = tile & 1;
        int nz  = nt * 48;                       // 48 x 16B per trajectory
        for (int c = tid; c < nz; c += CTPB) {
            int ti = c / 48, o = c - ti * 48;
            cp16(&zraw[buf][ti * ZSTRIDE + o * 16],
                 dbase + (size_t)(base_b + ti) * trajBytes
                       + (size_t)tile * (TS * 12) + o * 16);
        }
        // gain tile: 1536 B = 96 x 16B, one per thread
        cp16(((char*)kbuf[buf]) + tid * 16,
             ((const char*)g_k12) + (size_t)tile * (TS * 3 * 8) + tid * 16);
        if (tid < 48)
            cp16(((char*)sbuf[buf]) + tid * 16,
                 ((const char*)g_si) + (size_t)tile * (TS * 3 * 4) + tid * 16);
        cp_commit();
    };

    const float DTf = (float)(1.0 / 120.0);
    float a = 1.0f - dyna[1] * DTf;

    bool active = (tid < nt * 3);
    int  ti = tid / 3, sub = tid - 3 * ti;
    float x1 = 0.0f, x2 = 0.0f;
    if (active) {
        int b  = base_b + ti;
        int i1 = (sub == 2) ? 4 : sub;
        int i2 = (sub == 2) ? 5 : sub + 2;
        x1 = init[b * 6 + i1];
        x2 = init[b * 6 + i2];
    }
    double accd = 0.0;

    if (ntiles > 0) issue_tile(0);
    if (ntiles > 1) issue_tile(1);

    for (int tile = 0; tile < ntiles; ++tile) {
        int buf = tile & 1;
        cp_wait<1>();
        __syncthreads();
        if (active) {
            const float*  zp = (const float*)&zraw[buf][ti * ZSTRIDE];
            const float2* kp = kbuf[buf];
            const float*  sp = sbuf[buf];
            float facc = 0.0f;
#pragma unroll 8
            for (int t = 0; t < TS; ++t) {
                float2 k  = kp[t * 3 + sub];
                float siv = sp[t * 3 + sub];
                float z   = zp[t * 3 + sub];
                float xp1 = fmaf(DTf, x2, x1);
                float y   = z - xp1;
                x1 = fmaf(k.x, y, xp1);
                x2 = fmaf(k.y, y, a * x2);
                facc = fmaf(y * siv, y, facc);
            }
            accd += (double)facc;
        }
        __syncthreads();
        if (tile + 2 < ntiles) issue_tile(tile + 2);
    }

    // tail steps if T is not a multiple of TS (not hit for T=2048)
    if (active) {
        for (int t = ntiles * TS; t < Tt; ++t) {
            float2 k  = g_k12[t * 3 + sub];
            float siv = g_si [t * 3 + sub];
            float z   = __ldg((const float*)(dbase
                        + (size_t)(base_b + ti) * trajBytes) + t * 3 + sub);
            float xp1 = fmaf(DTf, x2, x1);
            float y   = z - xp1;
            x1 = fmaf(k.x, y, xp1);
            x2 = fmaf(k.y, y, a * x2);
            accd += (double)((y * siv) * y);
        }
    }

    // deterministic block reduction (reuse z smem)
    __syncthreads();
    double* sh = (double*)&zraw[0][0];
    sh[tid] = accd;
    __syncthreads();
    if (tid < 32) {
        double v = sh[tid] + sh[tid + 32] + sh[tid + 64];
#pragma unroll
        for (int off = 16; off > 0; off >>= 1)
            v += __shfl_down_sync(0xffffffffu, v, off);
        if (tid == 0) g_part[blockIdx.x] = v;
    }
}

// ---------------------------------------------------------------------------
// Final: deterministic fixed-order reduction of block partials.
// loss = sum_quad / (B*T) + sum_det / T
// ---------------------------------------------------------------------------
__global__ void ekf_final(float* __restrict__ out, int nblocks, int B, int T)
{
    double s = 0.0;
    for (int i = 0; i < nblocks; ++i) s += g_part[i];
    double res = s / ((double)B * (double)T) + g_sumdet / (double)T;
    out[0] = (float)res;
}

extern "C" void kernel_launch(void* const* d_in, const int* in_sizes, int n_in,
                              void* d_out, int out_size)
{
    const float* data = (const float*)d_in[0];
    const float* init = (const float*)d_in[1];
    const float* dyna = (const float*)d_in[2];
    const float* cov  = (const float*)d_in[3];

    int B = in_sizes[1] / 6;
    int T = in_sizes[0] / (B * 3);
    int Tt = (T > MAXT) ? MAXT : T;

    ekf_setup<<<1, 128>>>(dyna, cov, Tt);

    int blocks = (B + NTRAJ - 1) / NTRAJ;
    if (blocks > 256) blocks = 256;   // g_part capacity (147 expected)
    ekf_main<<<blocks, CTPB>>>(data, init, dyna, B, T);

    ekf_final<<<1, 1>>>((float*)d_out, blocks, B, T);
}